// round 5
// baseline (speedup 1.0000x reference)
#include <cuda_runtime.h>
#include <cstdint>

// ---------------------------------------------------------------------------
// SpatialWindowSelfAttention: b=2, img 256x256, C=256, 8 heads x 32, 8x8 windows
// All matmuls on tensor cores (mma.sync tf32 + ldmatrix), RN-rounded inputs.
// ---------------------------------------------------------------------------

#define IMG        256
#define BATCH      2
#define CDIM       256
#define NTOK       (BATCH * IMG * IMG)      // 131072
#define HEADS      8
#define HD         32
#define WS         64
#define NWIN       2048
#define QKV_DIM    (3 * CDIM)               // 768
#define GK         256

// Scratch
__device__ float g_wq [(size_t)QKV_DIM * CDIM];  // tf32-rounded wqkv
__device__ float g_wp [(size_t)CDIM * CDIM];     // tf32-rounded wp
__device__ float g_qkv[(size_t)NTOK * QKV_DIM];
__device__ float g_y  [(size_t)NTOK * CDIM];

// ---------------------------------------------------------------------------
// helpers
// ---------------------------------------------------------------------------
__device__ __forceinline__ uint32_t smem_u32(const void* p) {
    uint32_t a;
    asm("{ .reg .u64 t; cvta.to.shared.u64 t, %1; cvt.u32.u64 %0, t; }" : "=r"(a) : "l"(p));
    return a;
}
__device__ __forceinline__ float tf32_rn(float x) {
    uint32_t u;
    asm("cvt.rna.tf32.f32 %0, %1;" : "=r"(u) : "f"(x));
    return __uint_as_float(u);
}
__device__ __forceinline__ uint32_t tf32_rn_bits(uint32_t x) {
    uint32_t u;
    asm("cvt.rna.tf32.f32 %0, %1;" : "=r"(u) : "f"(__uint_as_float(x)));
    return u;
}
__device__ __forceinline__ void cp16(uint32_t s, const void* g) {
    asm volatile("cp.async.cg.shared.global [%0], [%1], 16;\n" :: "r"(s), "l"(g) : "memory");
}
#define CP_COMMIT() asm volatile("cp.async.commit_group;\n" ::: "memory")
template <int N>
__device__ __forceinline__ void cp_wait() {
    asm volatile("cp.async.wait_group %0;\n" :: "n"(N) : "memory");
}
__device__ __forceinline__ void ldsm4(uint32_t& r0, uint32_t& r1, uint32_t& r2,
                                      uint32_t& r3, uint32_t addr) {
    asm volatile("ldmatrix.sync.aligned.m8n8.x4.shared.b16 {%0,%1,%2,%3}, [%4];"
                 : "=r"(r0), "=r"(r1), "=r"(r2), "=r"(r3) : "r"(addr));
}
__device__ __forceinline__ void mma_tf32(float* d, const uint32_t* a, const uint32_t* b) {
    asm volatile(
        "mma.sync.aligned.m16n8k8.row.col.f32.tf32.tf32.f32 "
        "{%0,%1,%2,%3},{%4,%5,%6,%7},{%8,%9},{%0,%1,%2,%3};"
        : "+f"(d[0]), "+f"(d[1]), "+f"(d[2]), "+f"(d[3])
        : "r"(a[0]), "r"(a[1]), "r"(a[2]), "r"(a[3]), "r"(b[0]), "r"(b[1]));
}

// ---------------------------------------------------------------------------
// prep: round f32 array to tf32 (RN) — weights only (small)
// ---------------------------------------------------------------------------
__global__ void round_kernel(const float4* __restrict__ src, float4* __restrict__ dst, int n4)
{
    for (int i = blockIdx.x * blockDim.x + threadIdx.x; i < n4; i += gridDim.x * blockDim.x) {
        float4 v = src[i];
        v.x = tf32_rn(v.x); v.y = tf32_rn(v.y); v.z = tf32_rn(v.z); v.w = tf32_rn(v.w);
        dst[i] = v;
    }
}

// ---------------------------------------------------------------------------
// tf32 GEMM: C[m][n] = sum_k A[m][k]*B[n][k] + bias[n]
// RA: round A-fragments in-register post-ldmatrix (A is raw f32).
// RE: round epilogue output to tf32.
// ---------------------------------------------------------------------------
#define STAGE_B 32768
template<int RA, int RE>
__global__ void __launch_bounds__(256, 2)
gemm_mma_kernel(const float* __restrict__ A,
                const float* __restrict__ Bw,
                const float* __restrict__ bias,
                float* __restrict__ C, int N)
{
    extern __shared__ char sm[];
    const uint32_t sb = smem_u32(sm);

    const int tid  = threadIdx.x;
    const int lane = tid & 31;
    const int wid  = tid >> 5;
    const int g    = lane >> 2;
    const int t4   = lane & 3;
    const int wm   = (wid & 1) * 64;
    const int wn   = (wid >> 1) * 32;
    const int m0   = blockIdx.y * 128;
    const int n0   = blockIdx.x * 128;

    const char* Ag = (const char*)(A  + (size_t)m0 * GK);
    const char* Bg = (const char*)(Bw + (size_t)n0 * GK);

    float acc[4][4][4];
#pragma unroll
    for (int i = 0; i < 4; i++)
#pragma unroll
        for (int j = 0; j < 4; j++)
#pragma unroll
            for (int c = 0; c < 4; c++) acc[i][j][c] = 0.f;

    int rowA[4];
#pragma unroll
    for (int mf = 0; mf < 4; mf++) rowA[mf] = wm + mf * 16 + (lane & 15);
    const int haA = lane >> 4;
    int rowB[2];
#pragma unroll
    for (int p = 0; p < 2; p++) rowB[p] = wn + p * 16 + (lane & 7) + ((lane & 16) ? 8 : 0);
    const int haB = (lane >> 3) & 1;

    auto load_stage = [&](int it, int s) {
        const uint32_t sa = sb + (uint32_t)s * STAGE_B;
#pragma unroll
        for (int i = 0; i < 4; i++) {
            const int idx = tid + i * 256;
            const int row = idx >> 3, c = idx & 7;
            const uint32_t off = (uint32_t)(row * 128 + ((c ^ (row & 7)) << 4));
            const size_t goff = (size_t)row * 1024 + it * 128 + c * 16;
            cp16(sa + off, Ag + goff);
            cp16(sa + 16384 + off, Bg + goff);
        }
        CP_COMMIT();
    };

    load_stage(0, 0);
    load_stage(1, 1);
    load_stage(2, 2);

#pragma unroll 1
    for (int it = 0; it < 8; it++) {
        if (it < 6) cp_wait<2>();
        else if (it == 6) cp_wait<1>();
        else cp_wait<0>();
        __syncthreads();

        const uint32_t sa = sb + (uint32_t)(it % 3) * STAGE_B;
#pragma unroll
        for (int s4 = 0; s4 < 4; s4++) {
            uint32_t a[4][4], b[4][2];
#pragma unroll
            for (int mf = 0; mf < 4; mf++) {
                const int r = rowA[mf];
                ldsm4(a[mf][0], a[mf][1], a[mf][2], a[mf][3],
                      sa + r * 128 + (((2 * s4 + haA) ^ (r & 7)) << 4));
                if (RA) {
#pragma unroll
                    for (int e = 0; e < 4; e++) a[mf][e] = tf32_rn_bits(a[mf][e]);
                }
            }
#pragma unroll
            for (int p = 0; p < 2; p++) {
                const int r = rowB[p];
                uint32_t r0, r1, r2, r3;
                ldsm4(r0, r1, r2, r3,
                      sa + 16384 + r * 128 + (((2 * s4 + haB) ^ (r & 7)) << 4));
                b[2 * p][0] = r0; b[2 * p][1] = r1;
                b[2 * p + 1][0] = r2; b[2 * p + 1][1] = r3;
            }
#pragma unroll
            for (int mf = 0; mf < 4; mf++)
#pragma unroll
                for (int nf = 0; nf < 4; nf++)
                    mma_tf32(acc[mf][nf], a[mf], b[nf]);
        }
        __syncthreads();
        if (it + 3 < 8) load_stage(it + 3, it % 3);
    }

    // epilogue
#pragma unroll
    for (int mf = 0; mf < 4; mf++) {
        const int r0 = m0 + wm + mf * 16 + g;
        const int r1 = r0 + 8;
#pragma unroll
        for (int nf = 0; nf < 4; nf++) {
            const int col = n0 + wn + nf * 8 + 2 * t4;
            const float2 bv = *(const float2*)&bias[col];
            float2 o0, o1;
            o0.x = acc[mf][nf][0] + bv.x;
            o0.y = acc[mf][nf][1] + bv.y;
            o1.x = acc[mf][nf][2] + bv.x;
            o1.y = acc[mf][nf][3] + bv.y;
            if (RE) {
                o0.x = tf32_rn(o0.x); o0.y = tf32_rn(o0.y);
                o1.x = tf32_rn(o1.x); o1.y = tf32_rn(o1.y);
            }
            *(float2*)&C[(size_t)r0 * N + col] = o0;
            *(float2*)&C[(size_t)r1 * N + col] = o1;
        }
    }
}

// ---------------------------------------------------------------------------
// Window attention on tensor cores. Block = (window, head), 128 thr, 4 warps.
// smem: sc(16KB) aliases [qs(8KB)|ks(8KB)]; vT 8KB; bt ~1KB  => ~25KB/block.
// Q/K gathered via cp.async into swizzled smem.
// ---------------------------------------------------------------------------
__global__ __launch_bounds__(128, 6)
void attn_kernel(const float* __restrict__ qkv,
                 const float* __restrict__ bias_table,
                 float* __restrict__ y)
{
    __shared__ float smQKS[WS * WS];      // 16KB: qs+ks, later sc
    __shared__ float vT[HD * WS];         // 8KB
    __shared__ float bt[225];

    const uint32_t qsb = smem_u32(smQKS);
    const uint32_t ksb = qsb + 8192;
    const uint32_t scb = qsb;
    const uint32_t vtb = smem_u32(vT);

    const int tid  = threadIdx.x;
    const int lane = tid & 31;
    const int wid  = tid >> 5;
    const int g    = lane >> 2;
    const int t4   = lane & 3;
    const int w    = blockIdx.x;
    const int hh   = blockIdx.y;
    const int bb   = w >> 10;
    const int widx = w & 1023;
    const int wr   = widx >> 5;
    const int wc   = widx & 31;

    // ---- async-gather q, k into swizzled 128B rows ----
#pragma unroll
    for (int i = 0; i < 8; i++) {
        const int idx = tid + i * 128;
        const int sel = idx >> 9;               // 0=q, 1=k
        const int rem = idx & 511;
        const int t   = rem >> 3;
        const int c   = rem & 7;
        const int trw = t >> 3, tcl = t & 7;
        const size_t tok = (size_t)bb * (IMG * IMG)
                         + (size_t)(wr * 8 + trw) * IMG + (wc * 8 + tcl);
        cp16((sel ? ksb : qsb) + t * 128 + ((c ^ (t & 7)) << 4),
             &qkv[tok * QKV_DIM + sel * CDIM + hh * HD + c * 4]);
    }
    CP_COMMIT();

    for (int i = tid; i < 225; i += 128) bt[i] = bias_table[i * HEADS + hh];

    // ---- v: LDG + transposed swizzled STS (vT[dim][key], 256B rows) ----
#pragma unroll
    for (int i = 0; i < 4; i++) {
        const int idx = tid + i * 128;
        const int t = idx >> 3;
        const int c = idx & 7;
        const int trw = t >> 3, tcl = t & 7;
        const size_t tok = (size_t)bb * (IMG * IMG)
                         + (size_t)(wr * 8 + trw) * IMG + (wc * 8 + tcl);
        const float4 v4 = *(const float4*)&qkv[tok * QKV_DIM + 2 * CDIM + hh * HD + c * 4];
        const float vv[4] = {v4.x, v4.y, v4.z, v4.w};
#pragma unroll
        for (int e = 0; e < 4; e++) {
            const int row = c * 4 + e;
            const uint32_t dst = vtb + row * 256 + (((t >> 2) ^ (row & 7)) << 4) + (t & 3) * 4;
            *(float*)(uintptr_t)__cvta_shared_to_generic(dst) = vv[e];
        }
    }
    cp_wait<0>();
    __syncthreads();

    // ---- scores: warp handles 16 q-rows; accum in regs ----
    float s[8][4];
#pragma unroll
    for (int j = 0; j < 8; j++)
#pragma unroll
        for (int c = 0; c < 4; c++) s[j][c] = 0.f;

    {
        const int rA = wid * 16 + (lane & 15);
        const int haA = lane >> 4;
        const int haB = (lane >> 3) & 1;

#pragma unroll
        for (int s4 = 0; s4 < 4; s4++) {
            uint32_t a[4];
            ldsm4(a[0], a[1], a[2], a[3],
                  qsb + rA * 128 + (((2 * s4 + haA) ^ (rA & 7)) << 4));
#pragma unroll
            for (int p = 0; p < 4; p++) {
                const int r = p * 16 + (lane & 7) + ((lane & 16) ? 8 : 0);
                uint32_t b0, b1, b2, b3;
                ldsm4(b0, b1, b2, b3,
                      ksb + r * 128 + (((2 * s4 + haB) ^ (r & 7)) << 4));
                uint32_t bA[2] = {b0, b1}, bB[2] = {b2, b3};
                mma_tf32(s[2 * p], a, bA);
                mma_tf32(s[2 * p + 1], a, bB);
            }
        }
    }
    __syncthreads();   // all warps done reading qs/ks -> safe to overwrite with sc

    // ---- scale + bias, store scores to sc (aliased over qs/ks) ----
    {
        const float scale = 0.17677669529663687f;
        const int qr0 = wid * 16 + g;
        const int qr1 = qr0 + 8;
#pragma unroll
        for (int j = 0; j < 8; j++) {
            const int col = j * 8 + 2 * t4;
            const int ki = col >> 3, kj = col & 7;
            const int ki2 = (col + 1) >> 3, kj2 = (col + 1) & 7;
            {
                const int qi = qr0 >> 3, qj = qr0 & 7;
                float2 o;
                o.x = s[j][0] * scale + bt[(qi - ki + 7) * 15 + (qj - kj + 7)];
                o.y = s[j][1] * scale + bt[(qi - ki2 + 7) * 15 + (qj - kj2 + 7)];
                const int cgr = col >> 2;
                const uint32_t dst = scb + qr0 * 256 + ((cgr ^ (qr0 & 7)) << 4) + (t4 & 1) * 8;
                *(float2*)(uintptr_t)__cvta_shared_to_generic(dst) = o;
            }
            {
                const int qi = qr1 >> 3, qj = qr1 & 7;
                float2 o;
                o.x = s[j][2] * scale + bt[(qi - ki + 7) * 15 + (qj - kj + 7)];
                o.y = s[j][3] * scale + bt[(qi - ki2 + 7) * 15 + (qj - kj2 + 7)];
                const int cgr = col >> 2;
                const uint32_t dst = scb + qr1 * 256 + ((cgr ^ (qr1 & 7)) << 4) + (t4 & 1) * 8;
                *(float2*)(uintptr_t)__cvta_shared_to_generic(dst) = o;
            }
        }
    }
    __syncthreads();

    // ---- softmax: 2 threads per row; probs rounded to tf32 ----
    {
        const int row  = tid >> 1;
        const int half = tid & 1;
        float4 vv[8];
        float m = -1e30f;
#pragma unroll
        for (int j = 0; j < 8; j++) {
            const int c = half * 8 + j;
            const uint32_t a = scb + row * 256 + ((c ^ (row & 7)) << 4);
            vv[j] = *(const float4*)(uintptr_t)__cvta_shared_to_generic(a);
            m = fmaxf(m, fmaxf(fmaxf(vv[j].x, vv[j].y), fmaxf(vv[j].z, vv[j].w)));
        }
        const float mo = __shfl_xor_sync(0xffffffffu, m, 1);
        const float M = fmaxf(m, mo);
        float ssum = 0.f;
#pragma unroll
        for (int j = 0; j < 8; j++) {
            vv[j].x = __expf(vv[j].x - M); vv[j].y = __expf(vv[j].y - M);
            vv[j].z = __expf(vv[j].z - M); vv[j].w = __expf(vv[j].w - M);
            ssum += vv[j].x + vv[j].y + vv[j].z + vv[j].w;
        }
        const float so = __shfl_xor_sync(0xffffffffu, ssum, 1);
        const float inv = 1.f / (ssum + so);
#pragma unroll
        for (int j = 0; j < 8; j++) {
            const int c = half * 8 + j;
            float4 o;
            o.x = tf32_rn(vv[j].x * inv); o.y = tf32_rn(vv[j].y * inv);
            o.z = tf32_rn(vv[j].z * inv); o.w = tf32_rn(vv[j].w * inv);
            const uint32_t a = scb + row * 256 + ((c ^ (row & 7)) << 4);
            *(float4*)(uintptr_t)__cvta_shared_to_generic(a) = o;
        }
    }
    __syncthreads();

    // ---- AV: warp 16 q-rows; 4 n-tiles (32 dims) x 8 k-steps (64 keys) ----
    {
        float o[4][4];
#pragma unroll
        for (int j = 0; j < 4; j++)
#pragma unroll
            for (int c = 0; c < 4; c++) o[j][c] = 0.f;

        const int rA = wid * 16 + (lane & 15);
        const int haA = lane >> 4;
        const int haB = (lane >> 3) & 1;

#pragma unroll
        for (int s8 = 0; s8 < 8; s8++) {
            uint32_t a[4];
            const int cA = 2 * s8 + haA;
            ldsm4(a[0], a[1], a[2], a[3],
                  scb + rA * 256 + ((cA ^ (rA & 7)) << 4));
#pragma unroll
            for (int p = 0; p < 2; p++) {
                const int r = p * 16 + (lane & 7) + ((lane & 16) ? 8 : 0);
                const int cB = 2 * s8 + haB;
                uint32_t b0, b1, b2, b3;
                ldsm4(b0, b1, b2, b3,
                      vtb + r * 256 + ((cB ^ (r & 7)) << 4));
                uint32_t bA[2] = {b0, b1}, bB[2] = {b2, b3};
                mma_tf32(o[2 * p], a, bA);
                mma_tf32(o[2 * p + 1], a, bB);
            }
        }

        // write y (tf32-rounded for the next GEMM)
#pragma unroll
        for (int rr = 0; rr < 2; rr++) {
            const int qr = wid * 16 + g + rr * 8;
            const int trw = qr >> 3, tcl = qr & 7;
            const size_t tok = (size_t)bb * (IMG * IMG)
                             + (size_t)(wr * 8 + trw) * IMG + (wc * 8 + tcl);
            float* dst = &y[tok * CDIM + hh * HD];
#pragma unroll
            for (int j = 0; j < 4; j++) {
                const int col = j * 8 + 2 * t4;
                float2 ov;
                ov.x = tf32_rn(o[j][rr * 2 + 0]);
                ov.y = tf32_rn(o[j][rr * 2 + 1]);
                *(float2*)&dst[col] = ov;
            }
        }
    }
}

// ---------------------------------------------------------------------------
extern "C" void kernel_launch(void* const* d_in, const int* in_sizes, int n_in,
                              void* d_out, int out_size)
{
    (void)in_sizes; (void)n_in; (void)out_size;
    const float* x          = (const float*)d_in[0];
    const float* wqkv_w     = (const float*)d_in[3];
    const float* wqkv_b     = (const float*)d_in[4];
    const float* wp_w       = (const float*)d_in[5];
    const float* wp_b       = (const float*)d_in[6];
    const float* bias_table = (const float*)d_in[7];
    float* out = (float*)d_out;

    float *wqr, *wpr, *qkv_ptr, *y_ptr;
    cudaGetSymbolAddress((void**)&wqr, g_wq);
    cudaGetSymbolAddress((void**)&wpr, g_wp);
    cudaGetSymbolAddress((void**)&qkv_ptr, g_qkv);
    cudaGetSymbolAddress((void**)&y_ptr, g_y);

    cudaFuncSetAttribute(gemm_mma_kernel<1, 1>,
                         cudaFuncAttributeMaxDynamicSharedMemorySize, 3 * STAGE_B);
    cudaFuncSetAttribute(gemm_mma_kernel<0, 0>,
                         cudaFuncAttributeMaxDynamicSharedMemorySize, 3 * STAGE_B);

    // 0) round weights to tf32 (RN) — tiny
    round_kernel<<<256, 256>>>((const float4*)wqkv_w, (float4*)wqr, QKV_DIM * CDIM / 4);
    round_kernel<<<128, 256>>>((const float4*)wp_w, (float4*)wpr, CDIM * CDIM / 4);

    // 1) QKV projection (A=x rounded in-register; epilogue rounds to tf32)
    gemm_mma_kernel<1, 1><<<dim3(QKV_DIM / 128, NTOK / 128), 256, 3 * STAGE_B>>>(
        x, wqr, wqkv_b, qkv_ptr, QKV_DIM);

    // 2) windowed attention (tensor cores)
    attn_kernel<<<dim3(NWIN, HEADS), 128>>>(qkv_ptr, bias_table, y_ptr);

    // 3) output projection (A=y already tf32; final output, no rounding)
    gemm_mma_kernel<0, 0><<<dim3(CDIM / 128, NTOK / 128), 256, 3 * STAGE_B>>>(
        y_ptr, wpr, wp_b, out, CDIM);
}

// round 6
// speedup vs baseline: 1.4757x; 1.4757x over previous
#include <cuda_runtime.h>
#include <cstdint>

// ---------------------------------------------------------------------------
// SpatialWindowSelfAttention: b=2, img 256x256, C=256, 8 heads x 32, 8x8 windows
// All matmuls on tensor cores (mma.sync tf32 + ldmatrix), RN-rounded inputs.
// qkv scratch in window-major layout for fully-coalesced attention loads.
// ---------------------------------------------------------------------------

#define IMG        256
#define BATCH      2
#define CDIM       256
#define NTOK       (BATCH * IMG * IMG)      // 131072
#define HEADS      8
#define HD         32
#define WS         64
#define NWIN       2048
#define QKV_DIM    (3 * CDIM)               // 768
#define GK         256

// Scratch
__device__ float g_x  [(size_t)NTOK * CDIM];     // tf32-rounded x
__device__ float g_wq [(size_t)QKV_DIM * CDIM];  // tf32-rounded wqkv
__device__ float g_wp [(size_t)CDIM * CDIM];     // tf32-rounded wp
__device__ float g_qkv[(size_t)NTOK * QKV_DIM];  // window-major: [sel][head][win][tok][hd]
__device__ float g_y  [(size_t)NTOK * CDIM];     // token-major

// ---------------------------------------------------------------------------
// helpers
// ---------------------------------------------------------------------------
__device__ __forceinline__ uint32_t smem_u32(const void* p) {
    uint32_t a;
    asm("{ .reg .u64 t; cvta.to.shared.u64 t, %1; cvt.u32.u64 %0, t; }" : "=r"(a) : "l"(p));
    return a;
}
__device__ __forceinline__ float tf32_rn(float x) {
    uint32_t u;
    asm("cvt.rna.tf32.f32 %0, %1;" : "=r"(u) : "f"(x));
    return __uint_as_float(u);
}
__device__ __forceinline__ void cp16(uint32_t s, const void* g) {
    asm volatile("cp.async.cg.shared.global [%0], [%1], 16;\n" :: "r"(s), "l"(g) : "memory");
}
#define CP_COMMIT() asm volatile("cp.async.commit_group;\n" ::: "memory")
template <int N>
__device__ __forceinline__ void cp_wait() {
    asm volatile("cp.async.wait_group %0;\n" :: "n"(N) : "memory");
}
__device__ __forceinline__ void ldsm4(uint32_t& r0, uint32_t& r1, uint32_t& r2,
                                      uint32_t& r3, uint32_t addr) {
    asm volatile("ldmatrix.sync.aligned.m8n8.x4.shared.b16 {%0,%1,%2,%3}, [%4];"
                 : "=r"(r0), "=r"(r1), "=r"(r2), "=r"(r3) : "r"(addr));
}
__device__ __forceinline__ void mma_tf32(float* d, const uint32_t* a, const uint32_t* b) {
    asm volatile(
        "mma.sync.aligned.m16n8k8.row.col.f32.tf32.tf32.f32 "
        "{%0,%1,%2,%3},{%4,%5,%6,%7},{%8,%9},{%0,%1,%2,%3};"
        : "+f"(d[0]), "+f"(d[1]), "+f"(d[2]), "+f"(d[3])
        : "r"(a[0]), "r"(a[1]), "r"(a[2]), "r"(a[3]), "r"(b[0]), "r"(b[1]));
}

// ---------------------------------------------------------------------------
// prep: round f32 array to tf32 (RN)
// ---------------------------------------------------------------------------
__global__ void round_kernel(const float4* __restrict__ src, float4* __restrict__ dst, int n4)
{
    for (int i = blockIdx.x * blockDim.x + threadIdx.x; i < n4; i += gridDim.x * blockDim.x) {
        float4 v = src[i];
        v.x = tf32_rn(v.x); v.y = tf32_rn(v.y); v.z = tf32_rn(v.z); v.w = tf32_rn(v.w);
        dst[i] = v;
    }
}

// ---------------------------------------------------------------------------
// tf32 GEMM: C[m][n] = sum_k A[m][k]*B[n][k] + bias[n]
// RE: round epilogue output to tf32. SCATTER: write window-major qkv layout.
// ---------------------------------------------------------------------------
#define STAGE_B 32768
template<int RE, int SCATTER>
__global__ void __launch_bounds__(256, 2)
gemm_mma_kernel(const float* __restrict__ A,
                const float* __restrict__ Bw,
                const float* __restrict__ bias,
                float* __restrict__ C, int N)
{
    extern __shared__ char sm[];
    const uint32_t sb = smem_u32(sm);

    const int tid  = threadIdx.x;
    const int lane = tid & 31;
    const int wid  = tid >> 5;
    const int g    = lane >> 2;
    const int t4   = lane & 3;
    const int wm   = (wid & 1) * 64;
    const int wn   = (wid >> 1) * 32;
    const int m0   = blockIdx.y * 128;
    const int n0   = blockIdx.x * 128;

    const char* Ag = (const char*)(A  + (size_t)m0 * GK);
    const char* Bg = (const char*)(Bw + (size_t)n0 * GK);

    float acc[4][4][4];
#pragma unroll
    for (int i = 0; i < 4; i++)
#pragma unroll
        for (int j = 0; j < 4; j++)
#pragma unroll
            for (int c = 0; c < 4; c++) acc[i][j][c] = 0.f;

    int rowA[4];
#pragma unroll
    for (int mf = 0; mf < 4; mf++) rowA[mf] = wm + mf * 16 + (lane & 15);
    const int haA = lane >> 4;
    int rowB[2];
#pragma unroll
    for (int p = 0; p < 2; p++) rowB[p] = wn + p * 16 + (lane & 7) + ((lane & 16) ? 8 : 0);
    const int haB = (lane >> 3) & 1;

    auto load_stage = [&](int it, int s) {
        const uint32_t sa = sb + (uint32_t)s * STAGE_B;
#pragma unroll
        for (int i = 0; i < 4; i++) {
            const int idx = tid + i * 256;
            const int row = idx >> 3, c = idx & 7;
            const uint32_t off = (uint32_t)(row * 128 + ((c ^ (row & 7)) << 4));
            const size_t goff = (size_t)row * 1024 + it * 128 + c * 16;
            cp16(sa + off, Ag + goff);
            cp16(sa + 16384 + off, Bg + goff);
        }
        CP_COMMIT();
    };

    load_stage(0, 0);
    load_stage(1, 1);
    load_stage(2, 2);

#pragma unroll 1
    for (int it = 0; it < 8; it++) {
        if (it < 6) cp_wait<2>();
        else if (it == 6) cp_wait<1>();
        else cp_wait<0>();
        __syncthreads();

        const uint32_t sa = sb + (uint32_t)(it % 3) * STAGE_B;
#pragma unroll
        for (int s4 = 0; s4 < 4; s4++) {
            uint32_t a[4][4], b[4][2];
#pragma unroll
            for (int mf = 0; mf < 4; mf++) {
                const int r = rowA[mf];
                ldsm4(a[mf][0], a[mf][1], a[mf][2], a[mf][3],
                      sa + r * 128 + (((2 * s4 + haA) ^ (r & 7)) << 4));
            }
#pragma unroll
            for (int p = 0; p < 2; p++) {
                const int r = rowB[p];
                uint32_t r0, r1, r2, r3;
                ldsm4(r0, r1, r2, r3,
                      sa + 16384 + r * 128 + (((2 * s4 + haB) ^ (r & 7)) << 4));
                b[2 * p][0] = r0; b[2 * p][1] = r1;
                b[2 * p + 1][0] = r2; b[2 * p + 1][1] = r3;
            }
#pragma unroll
            for (int mf = 0; mf < 4; mf++)
#pragma unroll
                for (int nf = 0; nf < 4; nf++)
                    mma_tf32(acc[mf][nf], a[mf], b[nf]);
        }
        __syncthreads();
        if (it + 3 < 8) load_stage(it + 3, it % 3);
    }

    // epilogue
#pragma unroll
    for (int mf = 0; mf < 4; mf++) {
        const int r0 = m0 + wm + mf * 16 + g;
        const int r1 = r0 + 8;
        size_t tb0 = 0, tb1 = 0;
        if (SCATTER) {
            // token -> (win, tok-in-window)
            const int bb0 = r0 >> 16, px0 = r0 & 65535;
            const int win0 = bb0 * 1024 + ((px0 >> 8) >> 3) * 32 + ((px0 & 255) >> 3);
            const int tk0  = (((px0 >> 8) & 7) << 3) + (px0 & 7);
            tb0 = (size_t)win0 * (WS * HD) + tk0 * HD;
            const int bb1 = r1 >> 16, px1 = r1 & 65535;
            const int win1 = bb1 * 1024 + ((px1 >> 8) >> 3) * 32 + ((px1 & 255) >> 3);
            const int tk1  = (((px1 >> 8) & 7) << 3) + (px1 & 7);
            tb1 = (size_t)win1 * (WS * HD) + tk1 * HD;
        }
#pragma unroll
        for (int nf = 0; nf < 4; nf++) {
            const int col = n0 + wn + nf * 8 + 2 * t4;
            const float2 bv = *(const float2*)&bias[col];
            float2 o0, o1;
            o0.x = acc[mf][nf][0] + bv.x;
            o0.y = acc[mf][nf][1] + bv.y;
            o1.x = acc[mf][nf][2] + bv.x;
            o1.y = acc[mf][nf][3] + bv.y;
            if (RE) {
                o0.x = tf32_rn(o0.x); o0.y = tf32_rn(o0.y);
                o1.x = tf32_rn(o1.x); o1.y = tf32_rn(o1.y);
            }
            if (SCATTER) {
                // channel -> (sel, head, hd); heads 32-aligned so float2 stays inside
                const size_t ch = (size_t)(col >> 5) * (NWIN * WS * HD) + (col & 31);
                *(float2*)&C[ch + tb0] = o0;
                *(float2*)&C[ch + tb1] = o1;
            } else {
                *(float2*)&C[(size_t)r0 * N + col] = o0;
                *(float2*)&C[(size_t)r1 * N + col] = o1;
            }
        }
    }
}

// ---------------------------------------------------------------------------
// Window attention on tensor cores. Block = (window, head), 128 thr, 4 warps.
// qkv is window-major: q/k/v each a contiguous 8KB block per (win,head).
// smem: sc(16KB) aliases [qs|ks]; vT 8KB; bt ~1KB.
// ---------------------------------------------------------------------------
__global__ __launch_bounds__(128, 6)
void attn_kernel(const float* __restrict__ qkv,
                 const float* __restrict__ bias_table,
                 float* __restrict__ y)
{
    __shared__ float smQKS[WS * WS];      // 16KB: qs+ks, later sc
    __shared__ float vT[HD * WS];         // 8KB
    __shared__ float bt[225];

    const uint32_t qsb = smem_u32(smQKS);
    const uint32_t ksb = qsb + 8192;
    const uint32_t scb = qsb;
    const uint32_t vtb = smem_u32(vT);

    const int tid  = threadIdx.x;
    const int lane = tid & 31;
    const int wid  = tid >> 5;
    const int g    = lane >> 2;
    const int t4   = lane & 3;
    const int win  = blockIdx.x;
    const int hh   = blockIdx.y;

    const float* qg = qkv + ((size_t)(0 * HEADS + hh) * NWIN + win) * (WS * HD);
    const float* kg = qkv + ((size_t)(1 * HEADS + hh) * NWIN + win) * (WS * HD);
    const float* vg = qkv + ((size_t)(2 * HEADS + hh) * NWIN + win) * (WS * HD);

    // ---- async-load q, k (contiguous) into swizzled 128B rows ----
#pragma unroll
    for (int i = 0; i < 8; i++) {
        const int idx = tid + i * 128;
        const int sel = idx >> 9;               // 0=q, 1=k
        const int rem = idx & 511;
        const int t   = rem >> 3;
        const int c   = rem & 7;
        cp16((sel ? ksb : qsb) + t * 128 + ((c ^ (t & 7)) << 4),
             (sel ? kg : qg) + t * HD + c * 4);
    }
    CP_COMMIT();

    for (int i = tid; i < 225; i += 128) bt[i] = bias_table[i * HEADS + hh];

    // ---- v: contiguous LDG.128 + transposed swizzled STS ----
#pragma unroll
    for (int i = 0; i < 4; i++) {
        const int idx = tid + i * 128;
        const int t = idx >> 3;
        const int c = idx & 7;
        const float4 v4 = *(const float4*)(vg + t * HD + c * 4);
        const float vv[4] = {v4.x, v4.y, v4.z, v4.w};
#pragma unroll
        for (int e = 0; e < 4; e++) {
            const int row = c * 4 + e;
            const uint32_t dst = vtb + row * 256 + (((t >> 2) ^ (row & 7)) << 4) + (t & 3) * 4;
            *(float*)(uintptr_t)__cvta_shared_to_generic(dst) = vv[e];
        }
    }
    cp_wait<0>();
    __syncthreads();

    // ---- scores: warp handles 16 q-rows; accum in regs ----
    float s[8][4];
#pragma unroll
    for (int j = 0; j < 8; j++)
#pragma unroll
        for (int c = 0; c < 4; c++) s[j][c] = 0.f;

    {
        const int rA = wid * 16 + (lane & 15);
        const int haA = lane >> 4;
        const int haB = (lane >> 3) & 1;

#pragma unroll
        for (int s4 = 0; s4 < 4; s4++) {
            uint32_t a[4];
            ldsm4(a[0], a[1], a[2], a[3],
                  qsb + rA * 128 + (((2 * s4 + haA) ^ (rA & 7)) << 4));
#pragma unroll
            for (int p = 0; p < 4; p++) {
                const int r = p * 16 + (lane & 7) + ((lane & 16) ? 8 : 0);
                uint32_t b0, b1, b2, b3;
                ldsm4(b0, b1, b2, b3,
                      ksb + r * 128 + (((2 * s4 + haB) ^ (r & 7)) << 4));
                uint32_t bA[2] = {b0, b1}, bB[2] = {b2, b3};
                mma_tf32(s[2 * p], a, bA);
                mma_tf32(s[2 * p + 1], a, bB);
            }
        }
    }
    __syncthreads();   // qs/ks dead -> overwrite with sc

    // ---- scale + bias, store scores to sc ----
    {
        const float scale = 0.17677669529663687f;
        const int qr0 = wid * 16 + g;
        const int qr1 = qr0 + 8;
#pragma unroll
        for (int j = 0; j < 8; j++) {
            const int col = j * 8 + 2 * t4;
            const int ki = col >> 3, kj = col & 7;
            const int ki2 = (col + 1) >> 3, kj2 = (col + 1) & 7;
            {
                const int qi = qr0 >> 3, qj = qr0 & 7;
                float2 o;
                o.x = s[j][0] * scale + bt[(qi - ki + 7) * 15 + (qj - kj + 7)];
                o.y = s[j][1] * scale + bt[(qi - ki2 + 7) * 15 + (qj - kj2 + 7)];
                const int cgr = col >> 2;
                const uint32_t dst = scb + qr0 * 256 + ((cgr ^ (qr0 & 7)) << 4) + (t4 & 1) * 8;
                *(float2*)(uintptr_t)__cvta_shared_to_generic(dst) = o;
            }
            {
                const int qi = qr1 >> 3, qj = qr1 & 7;
                float2 o;
                o.x = s[j][2] * scale + bt[(qi - ki + 7) * 15 + (qj - kj + 7)];
                o.y = s[j][3] * scale + bt[(qi - ki2 + 7) * 15 + (qj - kj2 + 7)];
                const int cgr = col >> 2;
                const uint32_t dst = scb + qr1 * 256 + ((cgr ^ (qr1 & 7)) << 4) + (t4 & 1) * 8;
                *(float2*)(uintptr_t)__cvta_shared_to_generic(dst) = o;
            }
        }
    }
    __syncthreads();

    // ---- softmax: 2 threads per row; probs rounded to tf32 ----
    {
        const int row  = tid >> 1;
        const int half = tid & 1;
        float4 vv[8];
        float m = -1e30f;
#pragma unroll
        for (int j = 0; j < 8; j++) {
            const int c = half * 8 + j;
            const uint32_t a = scb + row * 256 + ((c ^ (row & 7)) << 4);
            vv[j] = *(const float4*)(uintptr_t)__cvta_shared_to_generic(a);
            m = fmaxf(m, fmaxf(fmaxf(vv[j].x, vv[j].y), fmaxf(vv[j].z, vv[j].w)));
        }
        const float mo = __shfl_xor_sync(0xffffffffu, m, 1);
        const float M = fmaxf(m, mo);
        float ssum = 0.f;
#pragma unroll
        for (int j = 0; j < 8; j++) {
            vv[j].x = __expf(vv[j].x - M); vv[j].y = __expf(vv[j].y - M);
            vv[j].z = __expf(vv[j].z - M); vv[j].w = __expf(vv[j].w - M);
            ssum += vv[j].x + vv[j].y + vv[j].z + vv[j].w;
        }
        const float so = __shfl_xor_sync(0xffffffffu, ssum, 1);
        const float inv = 1.f / (ssum + so);
#pragma unroll
        for (int j = 0; j < 8; j++) {
            const int c = half * 8 + j;
            float4 o;
            o.x = tf32_rn(vv[j].x * inv); o.y = tf32_rn(vv[j].y * inv);
            o.z = tf32_rn(vv[j].z * inv); o.w = tf32_rn(vv[j].w * inv);
            const uint32_t a = scb + row * 256 + ((c ^ (row & 7)) << 4);
            *(float4*)(uintptr_t)__cvta_shared_to_generic(a) = o;
        }
    }
    __syncthreads();

    // ---- AV ----
    {
        float o[4][4];
#pragma unroll
        for (int j = 0; j < 4; j++)
#pragma unroll
            for (int c = 0; c < 4; c++) o[j][c] = 0.f;

        const int rA = wid * 16 + (lane & 15);
        const int haA = lane >> 4;
        const int haB = (lane >> 3) & 1;

#pragma unroll
        for (int s8 = 0; s8 < 8; s8++) {
            uint32_t a[4];
            const int cA = 2 * s8 + haA;
            ldsm4(a[0], a[1], a[2], a[3],
                  scb + rA * 256 + ((cA ^ (rA & 7)) << 4));
#pragma unroll
            for (int p = 0; p < 2; p++) {
                const int r = p * 16 + (lane & 7) + ((lane & 16) ? 8 : 0);
                const int cB = 2 * s8 + haB;
                uint32_t b0, b1, b2, b3;
                ldsm4(b0, b1, b2, b3,
                      vtb + r * 256 + ((cB ^ (r & 7)) << 4));
                uint32_t bA[2] = {b0, b1}, bB[2] = {b2, b3};
                mma_tf32(o[2 * p], a, bA);
                mma_tf32(o[2 * p + 1], a, bB);
            }
        }

        // write y in token layout (tf32-rounded for GEMM2)
        const int bb = win >> 10;
        const int wr = (win >> 5) & 31;
        const int wc = win & 31;
#pragma unroll
        for (int rr = 0; rr < 2; rr++) {
            const int qr = wid * 16 + g + rr * 8;
            const int trw = qr >> 3, tcl = qr & 7;
            const size_t tok = (size_t)bb * (IMG * IMG)
                             + (size_t)(wr * 8 + trw) * IMG + (wc * 8 + tcl);
            float* dst = &y[tok * CDIM + hh * HD];
#pragma unroll
            for (int j = 0; j < 4; j++) {
                const int col = j * 8 + 2 * t4;
                float2 ov;
                ov.x = tf32_rn(o[j][rr * 2 + 0]);
                ov.y = tf32_rn(o[j][rr * 2 + 1]);
                *(float2*)&dst[col] = ov;
            }
        }
    }
}

// ---------------------------------------------------------------------------
extern "C" void kernel_launch(void* const* d_in, const int* in_sizes, int n_in,
                              void* d_out, int out_size)
{
    (void)in_sizes; (void)n_in; (void)out_size;
    const float* x          = (const float*)d_in[0];
    const float* wqkv_w     = (const float*)d_in[3];
    const float* wqkv_b     = (const float*)d_in[4];
    const float* wp_w       = (const float*)d_in[5];
    const float* wp_b       = (const float*)d_in[6];
    const float* bias_table = (const float*)d_in[7];
    float* out = (float*)d_out;

    float *xr, *wqr, *wpr, *qkv_ptr, *y_ptr;
    cudaGetSymbolAddress((void**)&xr, g_x);
    cudaGetSymbolAddress((void**)&wqr, g_wq);
    cudaGetSymbolAddress((void**)&wpr, g_wp);
    cudaGetSymbolAddress((void**)&qkv_ptr, g_qkv);
    cudaGetSymbolAddress((void**)&y_ptr, g_y);

    cudaFuncSetAttribute(gemm_mma_kernel<1, 1>,
                         cudaFuncAttributeMaxDynamicSharedMemorySize, 3 * STAGE_B);
    cudaFuncSetAttribute(gemm_mma_kernel<0, 0>,
                         cudaFuncAttributeMaxDynamicSharedMemorySize, 3 * STAGE_B);

    // 0) round inputs to tf32 (RN)
    round_kernel<<<4096, 256>>>((const float4*)x, (float4*)xr, NTOK * CDIM / 4);
    round_kernel<<<256, 256>>>((const float4*)wqkv_w, (float4*)wqr, QKV_DIM * CDIM / 4);
    round_kernel<<<128, 256>>>((const float4*)wp_w, (float4*)wpr, CDIM * CDIM / 4);

    // 1) QKV projection -> window-major qkv (epilogue rounds to tf32)
    gemm_mma_kernel<1, 1><<<dim3(QKV_DIM / 128, NTOK / 128), 256, 3 * STAGE_B>>>(
        xr, wqr, wqkv_b, qkv_ptr, QKV_DIM);

    // 2) windowed attention (tensor cores, contiguous loads)
    attn_kernel<<<dim3(NWIN, HEADS), 128>>>(qkv_ptr, bias_table, y_ptr);

    // 3) output projection (A=y already tf32; final output, no rounding)
    gemm_mma_kernel<0, 0><<<dim3(CDIM / 128, NTOK / 128), 256, 3 * STAGE_B>>>(
        y_ptr, wpr, wp_b, out, CDIM);
}

// round 7
// speedup vs baseline: 2.5414x; 1.7222x over previous
#include <cuda_runtime.h>
#include <cuda_fp16.h>
#include <cstdint>

// ---------------------------------------------------------------------------
// SpatialWindowSelfAttention: b=2, img 256x256, C=256, 8 heads x 32, 8x8 windows
// Full fp16 pipeline (RN-rounded inputs), fp32 accumulation, mma.sync m16n8k16.
// qkv scratch window-major fp16 for coalesced attention loads.
// ---------------------------------------------------------------------------

#define IMG        256
#define BATCH      2
#define CDIM       256
#define NTOK       (BATCH * IMG * IMG)      // 131072
#define HEADS      8
#define HD         32
#define WS         64
#define NWIN       2048
#define QKV_DIM    (3 * CDIM)               // 768
#define GK         256

// Scratch (device globals; no allocs allowed)
__device__ __half g_x  [(size_t)NTOK * CDIM];
__device__ __half g_wq [(size_t)QKV_DIM * CDIM];
__device__ __half g_wp [(size_t)CDIM * CDIM];
__device__ __half g_qkv[(size_t)NTOK * QKV_DIM];  // [sel][head][win][tok][hd]
__device__ __half g_y  [(size_t)NTOK * CDIM];     // token-major

// ---------------------------------------------------------------------------
// helpers
// ---------------------------------------------------------------------------
__device__ __forceinline__ uint32_t smem_u32(const void* p) {
    uint32_t a;
    asm("{ .reg .u64 t; cvta.to.shared.u64 t, %1; cvt.u32.u64 %0, t; }" : "=r"(a) : "l"(p));
    return a;
}
__device__ __forceinline__ void cp16(uint32_t s, const void* g) {
    asm volatile("cp.async.cg.shared.global [%0], [%1], 16;\n" :: "r"(s), "l"(g) : "memory");
}
#define CP_COMMIT() asm volatile("cp.async.commit_group;\n" ::: "memory")
template <int N>
__device__ __forceinline__ void cp_wait() {
    asm volatile("cp.async.wait_group %0;\n" :: "n"(N) : "memory");
}
__device__ __forceinline__ void ldsm4(uint32_t& r0, uint32_t& r1, uint32_t& r2,
                                      uint32_t& r3, uint32_t addr) {
    asm volatile("ldmatrix.sync.aligned.m8n8.x4.shared.b16 {%0,%1,%2,%3}, [%4];"
                 : "=r"(r0), "=r"(r1), "=r"(r2), "=r"(r3) : "r"(addr));
}
__device__ __forceinline__ void ldsm4t(uint32_t& r0, uint32_t& r1, uint32_t& r2,
                                       uint32_t& r3, uint32_t addr) {
    asm volatile("ldmatrix.sync.aligned.m8n8.x4.trans.shared.b16 {%0,%1,%2,%3}, [%4];"
                 : "=r"(r0), "=r"(r1), "=r"(r2), "=r"(r3) : "r"(addr));
}
__device__ __forceinline__ void mma_f16(float* d, const uint32_t* a, const uint32_t* b) {
    asm volatile(
        "mma.sync.aligned.m16n8k16.row.col.f32.f16.f16.f32 "
        "{%0,%1,%2,%3},{%4,%5,%6,%7},{%8,%9},{%0,%1,%2,%3};"
        : "+f"(d[0]), "+f"(d[1]), "+f"(d[2]), "+f"(d[3])
        : "r"(a[0]), "r"(a[1]), "r"(a[2]), "r"(a[3]), "r"(b[0]), "r"(b[1]));
}

// ---------------------------------------------------------------------------
// prep: convert f32 -> f16 (RN)
// ---------------------------------------------------------------------------
__global__ void cvt_half_kernel(const float4* __restrict__ src, uint2* __restrict__ dst, int n4)
{
    for (int i = blockIdx.x * blockDim.x + threadIdx.x; i < n4; i += gridDim.x * blockDim.x) {
        const float4 v = src[i];
        const __half2 h0 = __floats2half2_rn(v.x, v.y);
        const __half2 h1 = __floats2half2_rn(v.z, v.w);
        uint2 u;
        u.x = *(const uint32_t*)&h0;
        u.y = *(const uint32_t*)&h1;
        dst[i] = u;
    }
}

// ---------------------------------------------------------------------------
// fp16 GEMM: C[m][n] = sum_k A[m][k]*B[n][k] + bias[n], fp32 accum.
// A:[M][256] halves, B:[N][256] halves row-major. grid=(N/128, M/128), 256 thr.
// 8 warps 2m x 4n (warp tile 64x32). k-chunk 64 halves (128B rows), 3-stage
// cp.async, XOR-16B swizzle. NCHUNK = 4.
// OUTHALF: store __half (else float). SCATTER: window-major qkv scatter.
// ---------------------------------------------------------------------------
#define STAGE_B 32768
#define NCHUNK  4
template<int OUTHALF, int SCATTER>
__global__ void __launch_bounds__(256, 2)
gemm_mma_kernel(const __half* __restrict__ A,
                const __half* __restrict__ Bw,
                const float* __restrict__ bias,
                void* __restrict__ Cv, int N)
{
    extern __shared__ char sm[];
    const uint32_t sb = smem_u32(sm);

    const int tid  = threadIdx.x;
    const int lane = tid & 31;
    const int wid  = tid >> 5;
    const int g    = lane >> 2;
    const int t4   = lane & 3;
    const int wm   = (wid & 1) * 64;
    const int wn   = (wid >> 1) * 32;
    const int m0   = blockIdx.y * 128;
    const int n0   = blockIdx.x * 128;

    const char* Ag = (const char*)(A  + (size_t)m0 * GK);
    const char* Bg = (const char*)(Bw + (size_t)n0 * GK);

    float acc[4][4][4];
#pragma unroll
    for (int i = 0; i < 4; i++)
#pragma unroll
        for (int j = 0; j < 4; j++)
#pragma unroll
            for (int c = 0; c < 4; c++) acc[i][j][c] = 0.f;

    int rowA[4];
#pragma unroll
    for (int mf = 0; mf < 4; mf++) rowA[mf] = wm + mf * 16 + (lane & 15);
    const int haA = lane >> 4;
    int rowB[2];
#pragma unroll
    for (int p = 0; p < 2; p++) rowB[p] = wn + p * 16 + (lane & 7) + ((lane & 16) ? 8 : 0);
    const int haB = (lane >> 3) & 1;

    auto load_stage = [&](int it, int s) {
        const uint32_t sa = sb + (uint32_t)s * STAGE_B;
#pragma unroll
        for (int i = 0; i < 4; i++) {
            const int idx = tid + i * 256;
            const int row = idx >> 3, c = idx & 7;
            const uint32_t off = (uint32_t)(row * 128 + ((c ^ (row & 7)) << 4));
            const size_t goff = (size_t)row * (GK * 2) + it * 128 + c * 16;
            cp16(sa + off, Ag + goff);
            cp16(sa + 16384 + off, Bg + goff);
        }
        CP_COMMIT();
    };

    load_stage(0, 0);
    load_stage(1, 1);
    load_stage(2, 2);

#pragma unroll 1
    for (int it = 0; it < NCHUNK; it++) {
        if (it < NCHUNK - 2) cp_wait<2>();
        else if (it == NCHUNK - 2) cp_wait<1>();
        else cp_wait<0>();
        __syncthreads();

        const uint32_t sa = sb + (uint32_t)(it % 3) * STAGE_B;
#pragma unroll
        for (int s = 0; s < 4; s++) {          // 4 x k16 steps per 64-half chunk
            uint32_t a[4][4], b[4][2];
#pragma unroll
            for (int mf = 0; mf < 4; mf++) {
                const int r = rowA[mf];
                ldsm4(a[mf][0], a[mf][1], a[mf][2], a[mf][3],
                      sa + r * 128 + (((2 * s + haA) ^ (r & 7)) << 4));
            }
#pragma unroll
            for (int p = 0; p < 2; p++) {
                const int r = rowB[p];
                uint32_t r0, r1, r2, r3;
                ldsm4(r0, r1, r2, r3,
                      sa + 16384 + r * 128 + (((2 * s + haB) ^ (r & 7)) << 4));
                b[2 * p][0] = r0; b[2 * p][1] = r1;
                b[2 * p + 1][0] = r2; b[2 * p + 1][1] = r3;
            }
#pragma unroll
            for (int mf = 0; mf < 4; mf++)
#pragma unroll
                for (int nf = 0; nf < 4; nf++)
                    mma_f16(acc[mf][nf], a[mf], b[nf]);
        }
        __syncthreads();
        if (it + 3 < NCHUNK) load_stage(it + 3, it % 3);
    }

    // epilogue
#pragma unroll
    for (int mf = 0; mf < 4; mf++) {
        const int r0 = m0 + wm + mf * 16 + g;
        const int r1 = r0 + 8;
        size_t tb0 = 0, tb1 = 0;
        if (SCATTER) {
            const int bb0 = r0 >> 16, px0 = r0 & 65535;
            const int win0 = bb0 * 1024 + ((px0 >> 8) >> 3) * 32 + ((px0 & 255) >> 3);
            const int tk0  = (((px0 >> 8) & 7) << 3) + (px0 & 7);
            tb0 = (size_t)win0 * (WS * HD) + tk0 * HD;
            const int bb1 = r1 >> 16, px1 = r1 & 65535;
            const int win1 = bb1 * 1024 + ((px1 >> 8) >> 3) * 32 + ((px1 & 255) >> 3);
            const int tk1  = (((px1 >> 8) & 7) << 3) + (px1 & 7);
            tb1 = (size_t)win1 * (WS * HD) + tk1 * HD;
        }
#pragma unroll
        for (int nf = 0; nf < 4; nf++) {
            const int col = n0 + wn + nf * 8 + 2 * t4;
            const float2 bv = *(const float2*)&bias[col];
            float2 o0, o1;
            o0.x = acc[mf][nf][0] + bv.x;
            o0.y = acc[mf][nf][1] + bv.y;
            o1.x = acc[mf][nf][2] + bv.x;
            o1.y = acc[mf][nf][3] + bv.y;
            if (OUTHALF) {
                __half* C = (__half*)Cv;
                const __half2 h0 = __floats2half2_rn(o0.x, o0.y);
                const __half2 h1 = __floats2half2_rn(o1.x, o1.y);
                if (SCATTER) {
                    const size_t ch = (size_t)(col >> 5) * ((size_t)NWIN * WS * HD) + (col & 31);
                    *(__half2*)&C[ch + tb0] = h0;
                    *(__half2*)&C[ch + tb1] = h1;
                } else {
                    *(__half2*)&C[(size_t)r0 * N + col] = h0;
                    *(__half2*)&C[(size_t)r1 * N + col] = h1;
                }
            } else {
                float* C = (float*)Cv;
                *(float2*)&C[(size_t)r0 * N + col] = o0;
                *(float2*)&C[(size_t)r1 * N + col] = o1;
            }
        }
    }
}

// ---------------------------------------------------------------------------
// Window attention, fp16 tensor cores. Block = (window, head), 128 thr, 4 warps.
// smem (static, ~16.3KB):
//   qs:[0,5120) ks:[5120,10240) vs:[10240,15360)  pitch 80B rows (64B data+16 pad)
//   p16: aliases [0,9216)  pitch 144B rows
//   bt: [15360, +900)
// Softmax fully in registers (quad shfl).
// ---------------------------------------------------------------------------
__global__ __launch_bounds__(128, 8)
void attn_kernel(const __half* __restrict__ qkv,
                 const float* __restrict__ bias_table,
                 __half* __restrict__ y)
{
    __shared__ __align__(16) char sraw[15360 + 912];
    const uint32_t base = smem_u32(sraw);
    const uint32_t qsb = base;
    const uint32_t ksb = base + 5120;
    const uint32_t vsb = base + 10240;
    const uint32_t pb  = base;           // alias over qs+ks
    float* bt = (float*)(sraw + 15360);

    const int tid  = threadIdx.x;
    const int lane = tid & 31;
    const int wid  = tid >> 5;
    const int g    = lane >> 2;
    const int t4   = lane & 3;
    const int win  = blockIdx.x;
    const int hh   = blockIdx.y;

    const __half* qg = qkv + ((size_t)(0 * HEADS + hh) * NWIN + win) * (WS * HD);
    const __half* kg = qkv + ((size_t)(1 * HEADS + hh) * NWIN + win) * (WS * HD);
    const __half* vg = qkv + ((size_t)(2 * HEADS + hh) * NWIN + win) * (WS * HD);

    // ---- async-load q, k, v (contiguous 4KB each) into 80B-pitch rows ----
#pragma unroll
    for (int i = 0; i < 6; i++) {
        const int idx = tid + i * 128;
        const int sel = idx >> 8;           // 0=q,1=k,2=v
        const int rem = idx & 255;
        const int t   = rem >> 2;           // token
        const int c   = rem & 3;            // 16B chunk (8 halves)
        const __half* src = (sel == 0 ? qg : sel == 1 ? kg : vg) + t * HD + c * 8;
        const uint32_t dstb = (sel == 0 ? qsb : sel == 1 ? ksb : vsb);
        cp16(dstb + t * 80 + c * 16, src);
    }
    CP_COMMIT();

    for (int i = tid; i < 225; i += 128) bt[i] = bias_table[i * HEADS + hh];
    cp_wait<0>();
    __syncthreads();

    // ---- QK^T: warp owns q-rows [wid*16, +16); full 64 keys in regs ----
    float s[8][4];
#pragma unroll
    for (int j = 0; j < 8; j++)
#pragma unroll
        for (int c = 0; c < 4; c++) s[j][c] = 0.f;

    const int rA  = wid * 16 + (lane & 15);
    const int haA = lane >> 4;
    const int haB = (lane >> 3) & 1;

#pragma unroll
    for (int s2 = 0; s2 < 2; s2++) {        // k16 over head_dim 32
        uint32_t a[4];
        ldsm4(a[0], a[1], a[2], a[3], qsb + rA * 80 + (2 * s2 + haA) * 16);
#pragma unroll
        for (int p = 0; p < 4; p++) {       // 2 key n-tiles per x4
            const int r = p * 16 + (lane & 7) + ((lane & 16) ? 8 : 0);
            uint32_t b0, b1, b2, b3;
            ldsm4(b0, b1, b2, b3, ksb + r * 80 + (2 * s2 + haB) * 16);
            uint32_t bA[2] = {b0, b1}, bB[2] = {b2, b3};
            mma_f16(s[2 * p], a, bA);
            mma_f16(s[2 * p + 1], a, bB);
        }
    }

    // ---- scale + bias + softmax in regs (reduce across t4 quad) ----
    const float scale = 0.17677669529663687f;
    const int qlo = wid * 16 + g;
    const int qhi = qlo + 8;
    const int qi0 = qlo >> 3, qj0 = qlo & 7;
    const int qi1 = qhi >> 3, qj1 = qhi & 7;

    float mlo = -1e30f, mhi = -1e30f;
#pragma unroll
    for (int j = 0; j < 8; j++) {
        const int c0 = j * 8 + 2 * t4, c1 = c0 + 1;
        const int ki0 = c0 >> 3, kj0 = c0 & 7;
        const int ki1 = c1 >> 3, kj1 = c1 & 7;
        s[j][0] = s[j][0] * scale + bt[(qi0 - ki0 + 7) * 15 + (qj0 - kj0 + 7)];
        s[j][1] = s[j][1] * scale + bt[(qi0 - ki1 + 7) * 15 + (qj0 - kj1 + 7)];
        s[j][2] = s[j][2] * scale + bt[(qi1 - ki0 + 7) * 15 + (qj1 - kj0 + 7)];
        s[j][3] = s[j][3] * scale + bt[(qi1 - ki1 + 7) * 15 + (qj1 - kj1 + 7)];
        mlo = fmaxf(mlo, fmaxf(s[j][0], s[j][1]));
        mhi = fmaxf(mhi, fmaxf(s[j][2], s[j][3]));
    }
    mlo = fmaxf(mlo, __shfl_xor_sync(0xffffffffu, mlo, 1));
    mlo = fmaxf(mlo, __shfl_xor_sync(0xffffffffu, mlo, 2));
    mhi = fmaxf(mhi, __shfl_xor_sync(0xffffffffu, mhi, 1));
    mhi = fmaxf(mhi, __shfl_xor_sync(0xffffffffu, mhi, 2));

    float slo = 0.f, shi = 0.f;
#pragma unroll
    for (int j = 0; j < 8; j++) {
        s[j][0] = __expf(s[j][0] - mlo);
        s[j][1] = __expf(s[j][1] - mlo);
        s[j][2] = __expf(s[j][2] - mhi);
        s[j][3] = __expf(s[j][3] - mhi);
        slo += s[j][0] + s[j][1];
        shi += s[j][2] + s[j][3];
    }
    slo += __shfl_xor_sync(0xffffffffu, slo, 1);
    slo += __shfl_xor_sync(0xffffffffu, slo, 2);
    shi += __shfl_xor_sync(0xffffffffu, shi, 1);
    shi += __shfl_xor_sync(0xffffffffu, shi, 2);
    const float ilo = 1.f / slo, ihi = 1.f / shi;

    __syncthreads();   // all QK^T smem reads done -> p16 may overwrite qs/ks

    // ---- store P as fp16 into p16 (144B pitch) ----
#pragma unroll
    for (int j = 0; j < 8; j++) {
        const int c0 = j * 8 + 2 * t4;
        const __half2 plo = __floats2half2_rn(s[j][0] * ilo, s[j][1] * ilo);
        const __half2 phi = __floats2half2_rn(s[j][2] * ihi, s[j][3] * ihi);
        *(__half2*)(uintptr_t)__cvta_shared_to_generic(pb + qlo * 144 + c0 * 2) = plo;
        *(__half2*)(uintptr_t)__cvta_shared_to_generic(pb + qhi * 144 + c0 * 2) = phi;
    }
    __syncthreads();

    // ---- PV: A=P from p16, B=V via ldmatrix.trans from vs ----
    float o[4][4];
#pragma unroll
    for (int j = 0; j < 4; j++)
#pragma unroll
        for (int c = 0; c < 4; c++) o[j][c] = 0.f;

#pragma unroll
    for (int s2 = 0; s2 < 4; s2++) {        // k16 over 64 keys
        uint32_t a[4];
        ldsm4(a[0], a[1], a[2], a[3], pb + rA * 144 + (2 * s2 + haA) * 16);
#pragma unroll
        for (int p = 0; p < 2; p++) {       // 2 d n-tiles per x4.trans
            const int key = 16 * s2 + (lane & 7) + ((lane & 8) ? 8 : 0);
            const int chk = 2 * p + ((lane & 16) ? 1 : 0);
            uint32_t r0, r1, r2, r3;
            ldsm4t(r0, r1, r2, r3, vsb + key * 80 + chk * 16);
            uint32_t bA[2] = {r0, r1}, bB[2] = {r2, r3};
            mma_f16(o[2 * p], a, bA);
            mma_f16(o[2 * p + 1], a, bB);
        }
    }

    // ---- write y (fp16, token-major) ----
    {
        const int bb = win >> 10;
        const int wr = (win >> 5) & 31;
        const int wc = win & 31;
#pragma unroll
        for (int rr = 0; rr < 2; rr++) {
            const int qr = wid * 16 + g + rr * 8;
            const int trw = qr >> 3, tcl = qr & 7;
            const size_t tok = (size_t)bb * (IMG * IMG)
                             + (size_t)(wr * 8 + trw) * IMG + (wc * 8 + tcl);
            __half* dst = &y[tok * CDIM + hh * HD];
#pragma unroll
            for (int j = 0; j < 4; j++) {
                const int col = j * 8 + 2 * t4;
                const __half2 hv = __floats2half2_rn(o[j][rr * 2 + 0], o[j][rr * 2 + 1]);
                *(__half2*)&dst[col] = hv;
            }
        }
    }
}

// ---------------------------------------------------------------------------
extern "C" void kernel_launch(void* const* d_in, const int* in_sizes, int n_in,
                              void* d_out, int out_size)
{
    (void)in_sizes; (void)n_in; (void)out_size;
    const float* x          = (const float*)d_in[0];
    const float* wqkv_w     = (const float*)d_in[3];
    const float* wqkv_b     = (const float*)d_in[4];
    const float* wp_w       = (const float*)d_in[5];
    const float* wp_b       = (const float*)d_in[6];
    const float* bias_table = (const float*)d_in[7];
    float* out = (float*)d_out;

    __half *xh, *wqh, *wph, *qkv_ptr, *yh;
    cudaGetSymbolAddress((void**)&xh, g_x);
    cudaGetSymbolAddress((void**)&wqh, g_wq);
    cudaGetSymbolAddress((void**)&wph, g_wp);
    cudaGetSymbolAddress((void**)&qkv_ptr, g_qkv);
    cudaGetSymbolAddress((void**)&yh, g_y);

    cudaFuncSetAttribute(gemm_mma_kernel<1, 1>,
                         cudaFuncAttributeMaxDynamicSharedMemorySize, 3 * STAGE_B);
    cudaFuncSetAttribute(gemm_mma_kernel<0, 0>,
                         cudaFuncAttributeMaxDynamicSharedMemorySize, 3 * STAGE_B);

    // 0) convert inputs to fp16 (RN)
    cvt_half_kernel<<<4096, 256>>>((const float4*)x, (uint2*)xh, NTOK * CDIM / 4);
    cvt_half_kernel<<<256, 256>>>((const float4*)wqkv_w, (uint2*)wqh, QKV_DIM * CDIM / 4);
    cvt_half_kernel<<<128, 256>>>((const float4*)wp_w, (uint2*)wph, CDIM * CDIM / 4);

    // 1) QKV projection -> window-major fp16 qkv
    gemm_mma_kernel<1, 1><<<dim3(QKV_DIM / 128, NTOK / 128), 256, 3 * STAGE_B>>>(
        xh, wqh, wqkv_b, qkv_ptr, QKV_DIM);

    // 2) windowed attention (fp16 tensor cores)
    attn_kernel<<<dim3(NWIN, HEADS), 128>>>(qkv_ptr, bias_table, yh);

    // 3) output projection -> fp32 final output
    gemm_mma_kernel<0, 0><<<dim3(CDIM / 128, NTOK / 128), 256, 3 * STAGE_B>>>(
        yh, wph, wp_b, out, CDIM);
}

// round 8
// speedup vs baseline: 2.6159x; 1.0293x over previous
#include <cuda_runtime.h>
#include <cuda_fp16.h>
#include <cstdint>

// ---------------------------------------------------------------------------
// SpatialWindowSelfAttention: b=2, img 256x256, C=256, 8 heads x 32, 8x8 windows
// Full fp16 pipeline (RN-rounded inputs), fp32 accumulation, mma.sync m16n8k16.
// qkv scratch window-major fp16 for coalesced attention loads.
// ---------------------------------------------------------------------------

#define IMG        256
#define BATCH      2
#define CDIM       256
#define NTOK       (BATCH * IMG * IMG)      // 131072
#define HEADS      8
#define HD         32
#define WS         64
#define NWIN       2048
#define QKV_DIM    (3 * CDIM)               // 768
#define GK         256

// Scratch (device globals; no allocs allowed)
__device__ __half g_x  [(size_t)NTOK * CDIM];
__device__ __half g_wq [(size_t)QKV_DIM * CDIM];
__device__ __half g_wp [(size_t)CDIM * CDIM];
__device__ __half g_qkv[(size_t)NTOK * QKV_DIM];  // [sel][head][win][tok][hd]
__device__ __half g_y  [(size_t)NTOK * CDIM];     // token-major

// ---------------------------------------------------------------------------
// helpers
// ---------------------------------------------------------------------------
__device__ __forceinline__ uint32_t smem_u32(const void* p) {
    uint32_t a;
    asm("{ .reg .u64 t; cvta.to.shared.u64 t, %1; cvt.u32.u64 %0, t; }" : "=r"(a) : "l"(p));
    return a;
}
__device__ __forceinline__ void cp16(uint32_t s, const void* g) {
    asm volatile("cp.async.cg.shared.global [%0], [%1], 16;\n" :: "r"(s), "l"(g) : "memory");
}
#define CP_COMMIT() asm volatile("cp.async.commit_group;\n" ::: "memory")
template <int N>
__device__ __forceinline__ void cp_wait() {
    asm volatile("cp.async.wait_group %0;\n" :: "n"(N) : "memory");
}
__device__ __forceinline__ void ldsm4(uint32_t& r0, uint32_t& r1, uint32_t& r2,
                                      uint32_t& r3, uint32_t addr) {
    asm volatile("ldmatrix.sync.aligned.m8n8.x4.shared.b16 {%0,%1,%2,%3}, [%4];"
                 : "=r"(r0), "=r"(r1), "=r"(r2), "=r"(r3) : "r"(addr));
}
__device__ __forceinline__ void ldsm4t(uint32_t& r0, uint32_t& r1, uint32_t& r2,
                                       uint32_t& r3, uint32_t addr) {
    asm volatile("ldmatrix.sync.aligned.m8n8.x4.trans.shared.b16 {%0,%1,%2,%3}, [%4];"
                 : "=r"(r0), "=r"(r1), "=r"(r2), "=r"(r3) : "r"(addr));
}
__device__ __forceinline__ void mma_f16(float* d, const uint32_t* a, const uint32_t* b) {
    asm volatile(
        "mma.sync.aligned.m16n8k16.row.col.f32.f16.f16.f32 "
        "{%0,%1,%2,%3},{%4,%5,%6,%7},{%8,%9},{%0,%1,%2,%3};"
        : "+f"(d[0]), "+f"(d[1]), "+f"(d[2]), "+f"(d[3])
        : "r"(a[0]), "r"(a[1]), "r"(a[2]), "r"(a[3]), "r"(b[0]), "r"(b[1]));
}

// ---------------------------------------------------------------------------
// prep: convert f32 -> f16 (RN)
// ---------------------------------------------------------------------------
__global__ void cvt_half_kernel(const float4* __restrict__ src, uint2* __restrict__ dst, int n4)
{
    for (int i = blockIdx.x * blockDim.x + threadIdx.x; i < n4; i += gridDim.x * blockDim.x) {
        const float4 v = src[i];
        const __half2 h0 = __floats2half2_rn(v.x, v.y);
        const __half2 h1 = __floats2half2_rn(v.z, v.w);
        uint2 u;
        u.x = *(const uint32_t*)&h0;
        u.y = *(const uint32_t*)&h1;
        dst[i] = u;
    }
}

// ---------------------------------------------------------------------------
// fp16 GEMM: C[m][n] = sum_k A[m][k]*B[n][k] + bias[n], fp32 accum.
// 3 smem buffers, 2 loads in flight, ONE __syncthreads per chunk.
// OUTHALF: store __half (else float). SCATTER: window-major qkv scatter.
// ---------------------------------------------------------------------------
#define STAGE_B 32768
#define NCHUNK  4
template<int OUTHALF, int SCATTER>
__global__ void __launch_bounds__(256, 2)
gemm_mma_kernel(const __half* __restrict__ A,
                const __half* __restrict__ Bw,
                const float* __restrict__ bias,
                void* __restrict__ Cv, int N)
{
    extern __shared__ char sm[];
    const uint32_t sb = smem_u32(sm);

    const int tid  = threadIdx.x;
    const int lane = tid & 31;
    const int wid  = tid >> 5;
    const int g    = lane >> 2;
    const int t4   = lane & 3;
    const int wm   = (wid & 1) * 64;
    const int wn   = (wid >> 1) * 32;
    const int m0   = blockIdx.y * 128;
    const int n0   = blockIdx.x * 128;

    const char* Ag = (const char*)(A  + (size_t)m0 * GK);
    const char* Bg = (const char*)(Bw + (size_t)n0 * GK);

    float acc[4][4][4];
#pragma unroll
    for (int i = 0; i < 4; i++)
#pragma unroll
        for (int j = 0; j < 4; j++)
#pragma unroll
            for (int c = 0; c < 4; c++) acc[i][j][c] = 0.f;

    int rowA[4];
#pragma unroll
    for (int mf = 0; mf < 4; mf++) rowA[mf] = wm + mf * 16 + (lane & 15);
    const int haA = lane >> 4;
    int rowB[2];
#pragma unroll
    for (int p = 0; p < 2; p++) rowB[p] = wn + p * 16 + (lane & 7) + ((lane & 16) ? 8 : 0);
    const int haB = (lane >> 3) & 1;

    auto load_stage = [&](int it, int s) {
        const uint32_t sa = sb + (uint32_t)s * STAGE_B;
#pragma unroll
        for (int i = 0; i < 4; i++) {
            const int idx = tid + i * 256;
            const int row = idx >> 3, c = idx & 7;
            const uint32_t off = (uint32_t)(row * 128 + ((c ^ (row & 7)) << 4));
            const size_t goff = (size_t)row * (GK * 2) + it * 128 + c * 16;
            cp16(sa + off, Ag + goff);
            cp16(sa + 16384 + off, Bg + goff);
        }
        CP_COMMIT();
    };

    // 2 chunks in flight
    load_stage(0, 0);
    load_stage(1, 1);

#pragma unroll 1
    for (int it = 0; it < NCHUNK; it++) {
        if (it == NCHUNK - 1) cp_wait<0>();
        else                  cp_wait<1>();
        __syncthreads();     // chunk `it` resident; buffer (it+2)%3 free (computed it-1)

        if (it + 2 < NCHUNK) load_stage(it + 2, (it + 2) % 3);

        const uint32_t sa = sb + (uint32_t)(it % 3) * STAGE_B;
#pragma unroll
        for (int s = 0; s < 4; s++) {          // 4 x k16 steps per 64-half chunk
            uint32_t a[4][4], b[4][2];
#pragma unroll
            for (int mf = 0; mf < 4; mf++) {
                const int r = rowA[mf];
                ldsm4(a[mf][0], a[mf][1], a[mf][2], a[mf][3],
                      sa + r * 128 + (((2 * s + haA) ^ (r & 7)) << 4));
            }
#pragma unroll
            for (int p = 0; p < 2; p++) {
                const int r = rowB[p];
                uint32_t r0, r1, r2, r3;
                ldsm4(r0, r1, r2, r3,
                      sa + 16384 + r * 128 + (((2 * s + haB) ^ (r & 7)) << 4));
                b[2 * p][0] = r0; b[2 * p][1] = r1;
                b[2 * p + 1][0] = r2; b[2 * p + 1][1] = r3;
            }
#pragma unroll
            for (int mf = 0; mf < 4; mf++)
#pragma unroll
                for (int nf = 0; nf < 4; nf++)
                    mma_f16(acc[mf][nf], a[mf], b[nf]);
        }
    }

    // epilogue
#pragma unroll
    for (int mf = 0; mf < 4; mf++) {
        const int r0 = m0 + wm + mf * 16 + g;
        const int r1 = r0 + 8;
        size_t tb0 = 0, tb1 = 0;
        if (SCATTER) {
            const int bb0 = r0 >> 16, px0 = r0 & 65535;
            const int win0 = bb0 * 1024 + ((px0 >> 8) >> 3) * 32 + ((px0 & 255) >> 3);
            const int tk0  = (((px0 >> 8) & 7) << 3) + (px0 & 7);
            tb0 = (size_t)win0 * (WS * HD) + tk0 * HD;
            const int bb1 = r1 >> 16, px1 = r1 & 65535;
            const int win1 = bb1 * 1024 + ((px1 >> 8) >> 3) * 32 + ((px1 & 255) >> 3);
            const int tk1  = (((px1 >> 8) & 7) << 3) + (px1 & 7);
            tb1 = (size_t)win1 * (WS * HD) + tk1 * HD;
        }
#pragma unroll
        for (int nf = 0; nf < 4; nf++) {
            const int col = n0 + wn + nf * 8 + 2 * t4;
            const float2 bv = *(const float2*)&bias[col];
            float2 o0, o1;
            o0.x = acc[mf][nf][0] + bv.x;
            o0.y = acc[mf][nf][1] + bv.y;
            o1.x = acc[mf][nf][2] + bv.x;
            o1.y = acc[mf][nf][3] + bv.y;
            if (OUTHALF) {
                __half* C = (__half*)Cv;
                const __half2 h0 = __floats2half2_rn(o0.x, o0.y);
                const __half2 h1 = __floats2half2_rn(o1.x, o1.y);
                if (SCATTER) {
                    const size_t ch = (size_t)(col >> 5) * ((size_t)NWIN * WS * HD) + (col & 31);
                    *(__half2*)&C[ch + tb0] = h0;
                    *(__half2*)&C[ch + tb1] = h1;
                } else {
                    *(__half2*)&C[(size_t)r0 * N + col] = h0;
                    *(__half2*)&C[(size_t)r1 * N + col] = h1;
                }
            } else {
                float* C = (float*)Cv;
                *(float2*)&C[(size_t)r0 * N + col] = o0;
                *(float2*)&C[(size_t)r1 * N + col] = o1;
            }
        }
    }
}

// ---------------------------------------------------------------------------
// Window attention, fp16 tensor cores. Block = (window, head), 128 thr, 4 warps.
// smem (static, ~16.3KB):
//   qs:[0,5120) ks:[5120,10240) vs:[10240,15360)  pitch 80B rows (64B data+16 pad)
//   p16: aliases [0,9216)  pitch 144B rows
//   bt: [15360, +900)
// Softmax fully in registers (quad shfl).
// ---------------------------------------------------------------------------
__global__ __launch_bounds__(128, 8)
void attn_kernel(const __half* __restrict__ qkv,
                 const float* __restrict__ bias_table,
                 __half* __restrict__ y)
{
    __shared__ __align__(16) char sraw[15360 + 912];
    const uint32_t base = smem_u32(sraw);
    const uint32_t qsb = base;
    const uint32_t ksb = base + 5120;
    const uint32_t vsb = base + 10240;
    const uint32_t pb  = base;           // alias over qs+ks
    float* bt = (float*)(sraw + 15360);

    const int tid  = threadIdx.x;
    const int lane = tid & 31;
    const int wid  = tid >> 5;
    const int g    = lane >> 2;
    const int t4   = lane & 3;
    const int win  = blockIdx.x;
    const int hh   = blockIdx.y;

    const __half* qg = qkv + ((size_t)(0 * HEADS + hh) * NWIN + win) * (WS * HD);
    const __half* kg = qkv + ((size_t)(1 * HEADS + hh) * NWIN + win) * (WS * HD);
    const __half* vg = qkv + ((size_t)(2 * HEADS + hh) * NWIN + win) * (WS * HD);

    // ---- async-load q, k, v (contiguous 4KB each) into 80B-pitch rows ----
#pragma unroll
    for (int i = 0; i < 6; i++) {
        const int idx = tid + i * 128;
        const int sel = idx >> 8;           // 0=q,1=k,2=v
        const int rem = idx & 255;
        const int t   = rem >> 2;           // token
        const int c   = rem & 3;            // 16B chunk (8 halves)
        const __half* src = (sel == 0 ? qg : sel == 1 ? kg : vg) + t * HD + c * 8;
        const uint32_t dstb = (sel == 0 ? qsb : sel == 1 ? ksb : vsb);
        cp16(dstb + t * 80 + c * 16, src);
    }
    CP_COMMIT();

    for (int i = tid; i < 225; i += 128) bt[i] = bias_table[i * HEADS + hh];
    cp_wait<0>();
    __syncthreads();

    // ---- QK^T: warp owns q-rows [wid*16, +16); full 64 keys in regs ----
    float s[8][4];
#pragma unroll
    for (int j = 0; j < 8; j++)
#pragma unroll
        for (int c = 0; c < 4; c++) s[j][c] = 0.f;

    const int rA  = wid * 16 + (lane & 15);
    const int haA = lane >> 4;
    const int haB = (lane >> 3) & 1;

#pragma unroll
    for (int s2 = 0; s2 < 2; s2++) {        // k16 over head_dim 32
        uint32_t a[4];
        ldsm4(a[0], a[1], a[2], a[3], qsb + rA * 80 + (2 * s2 + haA) * 16);
#pragma unroll
        for (int p = 0; p < 4; p++) {       // 2 key n-tiles per x4
            const int r = p * 16 + (lane & 7) + ((lane & 16) ? 8 : 0);
            uint32_t b0, b1, b2, b3;
            ldsm4(b0, b1, b2, b3, ksb + r * 80 + (2 * s2 + haB) * 16);
            uint32_t bA[2] = {b0, b1}, bB[2] = {b2, b3};
            mma_f16(s[2 * p], a, bA);
            mma_f16(s[2 * p + 1], a, bB);
        }
    }

    // ---- scale + bias + softmax in regs (reduce across t4 quad) ----
    const float scale = 0.17677669529663687f;
    const int qlo = wid * 16 + g;
    const int qhi = qlo + 8;
    const int qi0 = qlo >> 3, qj0 = qlo & 7;
    const int qi1 = qhi >> 3, qj1 = qhi & 7;

    float mlo = -1e30f, mhi = -1e30f;
#pragma unroll
    for (int j = 0; j < 8; j++) {
        const int c0 = j * 8 + 2 * t4, c1 = c0 + 1;
        const int ki0 = c0 >> 3, kj0 = c0 & 7;
        const int ki1 = c1 >> 3, kj1 = c1 & 7;
        s[j][0] = s[j][0] * scale + bt[(qi0 - ki0 + 7) * 15 + (qj0 - kj0 + 7)];
        s[j][1] = s[j][1] * scale + bt[(qi0 - ki1 + 7) * 15 + (qj0 - kj1 + 7)];
        s[j][2] = s[j][2] * scale + bt[(qi1 - ki0 + 7) * 15 + (qj1 - kj0 + 7)];
        s[j][3] = s[j][3] * scale + bt[(qi1 - ki1 + 7) * 15 + (qj1 - kj1 + 7)];
        mlo = fmaxf(mlo, fmaxf(s[j][0], s[j][1]));
        mhi = fmaxf(mhi, fmaxf(s[j][2], s[j][3]));
    }
    mlo = fmaxf(mlo, __shfl_xor_sync(0xffffffffu, mlo, 1));
    mlo = fmaxf(mlo, __shfl_xor_sync(0xffffffffu, mlo, 2));
    mhi = fmaxf(mhi, __shfl_xor_sync(0xffffffffu, mhi, 1));
    mhi = fmaxf(mhi, __shfl_xor_sync(0xffffffffu, mhi, 2));

    float slo = 0.f, shi = 0.f;
#pragma unroll
    for (int j = 0; j < 8; j++) {
        s[j][0] = __expf(s[j][0] - mlo);
        s[j][1] = __expf(s[j][1] - mlo);
        s[j][2] = __expf(s[j][2] - mhi);
        s[j][3] = __expf(s[j][3] - mhi);
        slo += s[j][0] + s[j][1];
        shi += s[j][2] + s[j][3];
    }
    slo += __shfl_xor_sync(0xffffffffu, slo, 1);
    slo += __shfl_xor_sync(0xffffffffu, slo, 2);
    shi += __shfl_xor_sync(0xffffffffu, shi, 1);
    shi += __shfl_xor_sync(0xffffffffu, shi, 2);
    const float ilo = 1.f / slo, ihi = 1.f / shi;

    __syncthreads();   // all QK^T smem reads done -> p16 may overwrite qs/ks

    // ---- store P as fp16 into p16 (144B pitch) ----
#pragma unroll
    for (int j = 0; j < 8; j++) {
        const int c0 = j * 8 + 2 * t4;
        const __half2 plo = __floats2half2_rn(s[j][0] * ilo, s[j][1] * ilo);
        const __half2 phi = __floats2half2_rn(s[j][2] * ihi, s[j][3] * ihi);
        *(__half2*)(uintptr_t)__cvta_shared_to_generic(pb + qlo * 144 + c0 * 2) = plo;
        *(__half2*)(uintptr_t)__cvta_shared_to_generic(pb + qhi * 144 + c0 * 2) = phi;
    }
    __syncthreads();

    // ---- PV: A=P from p16, B=V via ldmatrix.trans from vs ----
    float o[4][4];
#pragma unroll
    for (int j = 0; j < 4; j++)
#pragma unroll
        for (int c = 0; c < 4; c++) o[j][c] = 0.f;

#pragma unroll
    for (int s2 = 0; s2 < 4; s2++) {        // k16 over 64 keys
        uint32_t a[4];
        ldsm4(a[0], a[1], a[2], a[3], pb + rA * 144 + (2 * s2 + haA) * 16);
#pragma unroll
        for (int p = 0; p < 2; p++) {       // 2 d n-tiles per x4.trans
            const int key = 16 * s2 + (lane & 7) + ((lane & 8) ? 8 : 0);
            const int chk = 2 * p + ((lane & 16) ? 1 : 0);
            uint32_t r0, r1, r2, r3;
            ldsm4t(r0, r1, r2, r3, vsb + key * 80 + chk * 16);
            uint32_t bA[2] = {r0, r1}, bB[2] = {r2, r3};
            mma_f16(o[2 * p], a, bA);
            mma_f16(o[2 * p + 1], a, bB);
        }
    }

    // ---- write y (fp16, token-major) ----
    {
        const int bb = win >> 10;
        const int wr = (win >> 5) & 31;
        const int wc = win & 31;
#pragma unroll
        for (int rr = 0; rr < 2; rr++) {
            const int qr = wid * 16 + g + rr * 8;
            const int trw = qr >> 3, tcl = qr & 7;
            const size_t tok = (size_t)bb * (IMG * IMG)
                             + (size_t)(wr * 8 + trw) * IMG + (wc * 8 + tcl);
            __half* dst = &y[tok * CDIM + hh * HD];
#pragma unroll
            for (int j = 0; j < 4; j++) {
                const int col = j * 8 + 2 * t4;
                const __half2 hv = __floats2half2_rn(o[j][rr * 2 + 0], o[j][rr * 2 + 1]);
                *(__half2*)&dst[col] = hv;
            }
        }
    }
}

// ---------------------------------------------------------------------------
extern "C" void kernel_launch(void* const* d_in, const int* in_sizes, int n_in,
                              void* d_out, int out_size)
{
    (void)in_sizes; (void)n_in; (void)out_size;
    const float* x          = (const float*)d_in[0];
    const float* wqkv_w     = (const float*)d_in[3];
    const float* wqkv_b     = (const float*)d_in[4];
    const float* wp_w       = (const float*)d_in[5];
    const float* wp_b       = (const float*)d_in[6];
    const float* bias_table = (const float*)d_in[7];
    float* out = (float*)d_out;

    __half *xh, *wqh, *wph, *qkv_ptr, *yh;
    cudaGetSymbolAddress((void**)&xh, g_x);
    cudaGetSymbolAddress((void**)&wqh, g_wq);
    cudaGetSymbolAddress((void**)&wph, g_wp);
    cudaGetSymbolAddress((void**)&qkv_ptr, g_qkv);
    cudaGetSymbolAddress((void**)&yh, g_y);

    cudaFuncSetAttribute(gemm_mma_kernel<1, 1>,
                         cudaFuncAttributeMaxDynamicSharedMemorySize, 3 * STAGE_B);
    cudaFuncSetAttribute(gemm_mma_kernel<0, 0>,
                         cudaFuncAttributeMaxDynamicSharedMemorySize, 3 * STAGE_B);

    // 0) convert inputs to fp16 (RN)
    cvt_half_kernel<<<4096, 256>>>((const float4*)x, (uint2*)xh, NTOK * CDIM / 4);
    cvt_half_kernel<<<256, 256>>>((const float4*)wqkv_w, (uint2*)wqh, QKV_DIM * CDIM / 4);
    cvt_half_kernel<<<128, 256>>>((const float4*)wp_w, (uint2*)wph, CDIM * CDIM / 4);

    // 1) QKV projection -> window-major fp16 qkv
    gemm_mma_kernel<1, 1><<<dim3(QKV_DIM / 128, NTOK / 128), 256, 3 * STAGE_B>>>(
        xh, wqh, wqkv_b, qkv_ptr, QKV_DIM);

    // 2) windowed attention (fp16 tensor cores)
    attn_kernel<<<dim3(NWIN, HEADS), 128>>>(qkv_ptr, bias_table, yh);

    // 3) output projection -> fp32 final output
    gemm_mma_kernel<0, 0><<<dim3(CDIM / 128, NTOK / 128), 256, 3 * STAGE_B>>>(
        yh, wph, wp_b, out, CDIM);
}